// round 2
// baseline (speedup 1.0000x reference)
#include <cuda_runtime.h>

// MPSClassifier: B=16384, D=784, BOND=5, OUT=10
// Per batch element b:
//   c0[r]   = (1-x[b,0])*CF[0,r] + x[b,0]*CF[1,r]
//   for d=1..782:  c <- c @ (C0_d + x[b,d]*(C1_d - C0_d))   (5x5)
//   vlast[l] = (1-x[b,783])*CL[l,0] + x[b,783]*CL[l,1]
//   res = c . vlast ;  out[b,o] = res*fc_w[o] + fc_b[o]

#define TPB   128
#define TILE  56          // 784 = 14 * 56
#define XPAD  (TILE + 1)  // 57 -> conflict-free column reads
#define SITE  56          // floats per mid-site in smem: 25 C0, pad3, 25 D1, pad3
#define NMID  782
#define DIM   784
#define BATCH 16384
#define NOUT  10

__global__ __launch_bounds__(TPB, 1)
void mps_kernel(const float* __restrict__ x,
                const float* __restrict__ core_first,
                const float* __restrict__ cores_mid,
                const float* __restrict__ core_last,
                const float* __restrict__ fc_w,
                const float* __restrict__ fc_b,
                float* __restrict__ out)
{
    extern __shared__ float smem[];
    float* s_cores = smem;                       // NMID * SITE floats (175 KB)
    float* s_x     = smem + NMID * SITE;         // TPB * XPAD floats (29 KB)

    const int tid = threadIdx.x;
    const int b   = blockIdx.x * TPB + tid;

    // ---- cooperative load of mid cores: C0 and D1 = C1 - C0 ----
    // global layout: cores_mid[m][l][i][r] at m*50 + l*10 + i*5 + r
    for (int idx = tid; idx < NMID * 25; idx += TPB) {
        int m  = idx / 25;
        int lr = idx - m * 25;
        int l  = lr / 5;
        int r  = lr - l * 5;
        float c0 = cores_mid[m * 50 + l * 10 + r];
        float c1 = cores_mid[m * 50 + l * 10 + 5 + r];
        s_cores[m * SITE + lr]      = c0;
        s_cores[m * SITE + 28 + lr] = c1 - c0;
    }

    // ---- boundary cores into registers ----
    float cf0[5], cfd[5], cl0[5], cld[5];
#pragma unroll
    for (int r = 0; r < 5; r++) {
        float a = core_first[r];
        float bb = core_first[5 + r];
        cf0[r] = a;  cfd[r] = bb - a;
    }
#pragma unroll
    for (int l = 0; l < 5; l++) {
        float a = core_last[l * 2];
        float bb = core_last[l * 2 + 1];
        cl0[l] = a;  cld[l] = bb - a;
    }

    float c[5];
    float res = 0.0f;

    for (int t0 = 0; t0 < DIM; t0 += TILE) {
        __syncthreads();   // protect previous tile readers (and cores store on iter 0)
        // ---- coalesced load of x tile: rows b0..b0+127, cols t0..t0+55 ----
        for (int idx = tid; idx < TPB * TILE; idx += TPB) {
            int rr = idx / TILE;
            int cc = idx - rr * TILE;
            s_x[rr * XPAD + cc] =
                x[(size_t)(blockIdx.x * TPB + rr) * DIM + t0 + cc];
        }
        __syncthreads();

        const float* xrow = s_x + tid * XPAD;

        int dd  = 0;
        int dhi = TILE;
        if (t0 == 0) {
            // site 0: initialize carry
            float xv = xrow[0];
#pragma unroll
            for (int r = 0; r < 5; r++) c[r] = fmaf(xv, cfd[r], cf0[r]);
            dd = 1;
        }
        if (t0 + TILE >= DIM) dhi = TILE - 1;   // reserve last col for final site

        const float* cs = s_cores + (size_t)(t0 + dd - 1) * SITE;
        for (; dd < dhi; dd++, cs += SITE) {
            float xv = xrow[dd];
            float v0[5], v1[5];
#pragma unroll
            for (int r = 0; r < 5; r++) {
                v0[r] = c[0] * cs[r];
                v1[r] = c[0] * cs[28 + r];
            }
#pragma unroll
            for (int l = 1; l < 5; l++) {
#pragma unroll
                for (int r = 0; r < 5; r++) {
                    v0[r] = fmaf(c[l], cs[l * 5 + r],      v0[r]);
                    v1[r] = fmaf(c[l], cs[28 + l * 5 + r], v1[r]);
                }
            }
#pragma unroll
            for (int r = 0; r < 5; r++) c[r] = fmaf(xv, v1[r], v0[r]);
        }

        if (t0 + TILE >= DIM) {
            // site 783: contract with last core
            float xv  = xrow[TILE - 1];
            float acc = 0.0f;
#pragma unroll
            for (int l = 0; l < 5; l++)
                acc = fmaf(c[l], fmaf(xv, cld[l], cl0[l]), acc);
            res = acc;
        }
    }

    // ---- FC epilogue ----
#pragma unroll
    for (int o = 0; o < NOUT; o++)
        out[(size_t)b * NOUT + o] = fmaf(res, fc_w[o], fc_b[o]);
}

extern "C" void kernel_launch(void* const* d_in, const int* in_sizes, int n_in,
                              void* d_out, int out_size)
{
    const float* x          = (const float*)d_in[0];
    const float* core_first = (const float*)d_in[1];
    const float* cores_mid  = (const float*)d_in[2];
    const float* core_last  = (const float*)d_in[3];
    const float* fc_w       = (const float*)d_in[4];
    const float* fc_b       = (const float*)d_in[5];
    float* out              = (float*)d_out;

    const int smem_bytes = (NMID * SITE + TPB * XPAD) * (int)sizeof(float); // 204,352 B
    cudaFuncSetAttribute(mps_kernel, cudaFuncAttributeMaxDynamicSharedMemorySize,
                         smem_bytes);

    mps_kernel<<<BATCH / TPB, TPB, smem_bytes>>>(
        x, core_first, cores_mid, core_last, fc_w, fc_b, out);
}

// round 7
// speedup vs baseline: 1.2869x; 1.2869x over previous
#include <cuda_runtime.h>

// MPSClassifier: B=16384, D=784, BOND=5, OUT=10
// Split the sequential chain in half:
//   forward  : c = (site0) ; c <- c M_d   for d=1..391      (row vector)
//   backward : w = (site783); w <- M_d w  for d=782..392    (col vector)
//   res[b] = c . w ; out[b,o] = res*fc_w[o] + fc_b[o]
// M_d = C0_m + x[b,d] * (C1_m - C0_m), m = d-1.

#define TPB   128
#define TILE  56
#define XPAD  (TILE + 1)   // conflict-free x column reads
#define SITE  56           // per-site smem floats: 25 C0, pad3, 25 D1, pad3 (14 float4)
#define DIM   784
#define BATCH 16384
#define NOUT  10
#define NBLK  (BATCH / TPB)   // 128 forward + 128 backward

__device__ float g_fwd[5 * BATCH];
__device__ float g_bwd[5 * BATCH];

__global__ __launch_bounds__(TPB, 2)
void mps_chain(const float* __restrict__ x,
               const float* __restrict__ core_first,
               const float* __restrict__ cores_mid,
               const float* __restrict__ core_last)
{
    extern __shared__ float smem[];
    float* s_cores = smem;                    // TILE * SITE = 3136 floats (12.25 KB)
    float* s_x     = smem + TILE * SITE;      // TPB * XPAD  = 7296 floats (28.5 KB)

    const int  tid = threadIdx.x;
    const bool bwd = blockIdx.x >= NBLK;
    const int  blk = bwd ? blockIdx.x - NBLK : blockIdx.x;
    const int  b   = blk * TPB + tid;

    float c[5];

    if (!bwd) {
        // ================= FORWARD: sites 0..391 =================
        for (int t0 = 0; t0 < 392; t0 += TILE) {
            __syncthreads();
            for (int idx = tid; idx < TPB * TILE; idx += TPB) {
                int rr = idx / TILE, cc = idx - rr * TILE;
                s_x[rr * XPAD + cc] = x[(size_t)(blk * TPB + rr) * DIM + t0 + cc];
            }
            for (int idx = tid; idx < TILE * 25; idx += TPB) {
                int j = idx / 25, lr = idx - j * 25;
                int m = t0 - 1 + j;                     // site d = t0+j uses mid core m=d-1
                if (m >= 0) {
                    int l = lr / 5, r = lr - l * 5;
                    float a0 = cores_mid[m * 50 + l * 10 + r];
                    float a1 = cores_mid[m * 50 + l * 10 + 5 + r];
                    s_cores[j * SITE + lr]      = a0;
                    s_cores[j * SITE + 28 + lr] = a1 - a0;
                }
            }
            __syncthreads();

            const float* xrow = s_x + tid * XPAD;
            int j0 = 0;
            if (t0 == 0) {
                float xv = xrow[0];
#pragma unroll
                for (int r = 0; r < 5; r++)
                    c[r] = fmaf(xv, core_first[5 + r] - core_first[r], core_first[r]);
                j0 = 1;
            }
#pragma unroll 2
            for (int j = j0; j < TILE; j++) {
                float4 q[14];
                const float4* cp = (const float4*)(s_cores + j * SITE);
#pragma unroll
                for (int k = 0; k < 14; k++) q[k] = cp[k];
                const float* cs = (const float*)q;
                float xv = xrow[j];
                float v0[5], v1[5];
#pragma unroll
                for (int r = 0; r < 5; r++) {
                    v0[r] = c[0] * cs[r];
                    v1[r] = c[0] * cs[28 + r];
                }
#pragma unroll
                for (int l = 1; l < 5; l++)
#pragma unroll
                    for (int r = 0; r < 5; r++) {
                        v0[r] = fmaf(c[l], cs[l * 5 + r],      v0[r]);
                        v1[r] = fmaf(c[l], cs[28 + l * 5 + r], v1[r]);
                    }
#pragma unroll
                for (int r = 0; r < 5; r++) c[r] = fmaf(xv, v1[r], v0[r]);
            }
        }
#pragma unroll
        for (int r = 0; r < 5; r++) g_fwd[r * BATCH + b] = c[r];
    } else {
        // ================= BACKWARD: sites 783..392 =================
        for (int t0 = 728; t0 >= 392; t0 -= TILE) {
            __syncthreads();
            for (int idx = tid; idx < TPB * TILE; idx += TPB) {
                int rr = idx / TILE, cc = idx - rr * TILE;
                s_x[rr * XPAD + cc] = x[(size_t)(blk * TPB + rr) * DIM + t0 + cc];
            }
            for (int idx = tid; idx < TILE * 25; idx += TPB) {
                int j = idx / 25, lr = idx - j * 25;
                int m = t0 - 1 + j;
                if (m <= 781) {
                    int l = lr / 5, r = lr - l * 5;
                    float a0 = cores_mid[m * 50 + l * 10 + r];
                    float a1 = cores_mid[m * 50 + l * 10 + 5 + r];
                    s_cores[j * SITE + lr]      = a0;
                    s_cores[j * SITE + 28 + lr] = a1 - a0;
                }
            }
            __syncthreads();

            const float* xrow = s_x + tid * XPAD;
            int jhi = TILE - 1;
            if (t0 == 728) {                       // j=55 -> d=783: init from core_last
                float xv = xrow[TILE - 1];
#pragma unroll
                for (int l = 0; l < 5; l++)
                    c[l] = fmaf(xv, core_last[l * 2 + 1] - core_last[l * 2], core_last[l * 2]);
                jhi = TILE - 2;
            }
#pragma unroll 2
            for (int j = jhi; j >= 0; j--) {       // w <- M_d w
                float4 q[14];
                const float4* cp = (const float4*)(s_cores + j * SITE);
#pragma unroll
                for (int k = 0; k < 14; k++) q[k] = cp[k];
                const float* cs = (const float*)q;
                float xv = xrow[j];
                float v0[5], v1[5];
#pragma unroll
                for (int l = 0; l < 5; l++) {
                    v0[l] = cs[l * 5]      * c[0];
                    v1[l] = cs[28 + l * 5] * c[0];
                }
#pragma unroll
                for (int r = 1; r < 5; r++)
#pragma unroll
                    for (int l = 0; l < 5; l++) {
                        v0[l] = fmaf(cs[l * 5 + r],      c[r], v0[l]);
                        v1[l] = fmaf(cs[28 + l * 5 + r], c[r], v1[l]);
                    }
#pragma unroll
                for (int l = 0; l < 5; l++) c[l] = fmaf(xv, v1[l], v0[l]);
            }
        }
#pragma unroll
        for (int l = 0; l < 5; l++) g_bwd[l * BATCH + b] = c[l];
    }
}

__global__ __launch_bounds__(256)
void mps_epilogue(const float* __restrict__ fc_w,
                  const float* __restrict__ fc_b,
                  float* __restrict__ out)
{
    const int b = blockIdx.x * 256 + threadIdx.x;
    float acc = 0.0f;
#pragma unroll
    for (int r = 0; r < 5; r++)
        acc = fmaf(g_fwd[r * BATCH + b], g_bwd[r * BATCH + b], acc);
#pragma unroll
    for (int o = 0; o < NOUT; o++)
        out[(size_t)b * NOUT + o] = fmaf(acc, fc_w[o], fc_b[o]);
}

extern "C" void kernel_launch(void* const* d_in, const int* in_sizes, int n_in,
                              void* d_out, int out_size)
{
    const float* x          = (const float*)d_in[0];
    const float* core_first = (const float*)d_in[1];
    const float* cores_mid  = (const float*)d_in[2];
    const float* core_last  = (const float*)d_in[3];
    const float* fc_w       = (const float*)d_in[4];
    const float* fc_b       = (const float*)d_in[5];
    float* out              = (float*)d_out;

    const int smem_bytes = (TILE * SITE + TPB * XPAD) * (int)sizeof(float); // 41,728 B
    cudaFuncSetAttribute(mps_chain, cudaFuncAttributeMaxDynamicSharedMemorySize,
                         smem_bytes);

    mps_chain<<<2 * NBLK, TPB, smem_bytes>>>(x, core_first, cores_mid, core_last);
    mps_epilogue<<<BATCH / 256, 256>>>(fc_w, fc_b, out);
}